// round 16
// baseline (speedup 1.0000x reference)
#include <cuda_runtime.h>
#include <cuda_bf16.h>
#include <math.h>

#define SQ   2048
#define DIM  1024
#define NH   16
#define HD   64
#define FACT 16

// ---- scratch (device globals: the sanctioned no-alloc scratch path) ----
__device__ float g_V[NH * SQ * HD];              // 8 MB fp32 [h][s][hd]
__device__ float2 g_cand[(size_t)NH * SQ * 256]; // 67 MB: 16 tiles x 16 (val,idx)
__device__ float g_vsum[NH * HD];
__device__ float g_vsum_part[64][HD];

// bf16 split planes
__device__ __nv_bfloat16 g_xh[SQ * DIM],  g_xl[SQ * DIM];
__device__ __nv_bfloat16 g_ath[SQ * DIM], g_atl[SQ * DIM];   // attn out planes
__device__ __nv_bfloat16 g_WTh[4 * DIM * DIM], g_WTl[4 * DIM * DIM];
__device__ __nv_bfloat16 g_Qh[NH * SQ * HD], g_Ql[NH * SQ * HD];
__device__ __nv_bfloat16 g_Kh[NH * SQ * HD], g_Kl[NH * SQ * HD];

// ============================================================
// helpers
// ============================================================
__device__ __forceinline__ void bsplit(float v, __nv_bfloat16& h, __nv_bfloat16& l) {
    h = __float2bfloat16(v);
    l = __float2bfloat16(v - __bfloat162float(h));
}

__device__ __forceinline__ void mma_bf16(float* c, const unsigned* a, const unsigned* b) {
    asm volatile(
        "mma.sync.aligned.m16n8k16.row.col.f32.bf16.bf16.f32 "
        "{%0,%1,%2,%3}, {%4,%5,%6,%7}, {%8,%9}, {%0,%1,%2,%3};"
        : "+f"(c[0]), "+f"(c[1]), "+f"(c[2]), "+f"(c[3])
        : "r"(a[0]), "r"(a[1]), "r"(a[2]), "r"(a[3]),
          "r"(b[0]), "r"(b[1]));
}

#define LDSM4(R0, R1, R2, R3, A)                                          \
    asm volatile("ldmatrix.sync.aligned.m8n8.x4.shared.b16 "              \
                 "{%0,%1,%2,%3}, [%4];"                                   \
                 : "=r"(R0), "=r"(R1), "=r"(R2), "=r"(R3) : "r"(A))

// ============================================================
// fused 4x 1024x1024 transpose + bf16 hi/lo split (z = which W)
// ============================================================
__global__ __launch_bounds__(256) void transpose_split4(
    const float* __restrict__ W0, const float* __restrict__ W1,
    const float* __restrict__ W2, const float* __restrict__ W3,
    __nv_bfloat16* __restrict__ Dh, __nv_bfloat16* __restrict__ Dl)
{
    __shared__ float tile[32][33];
    const int z = blockIdx.z;
    const float* S = (z == 0) ? W0 : (z == 1) ? W1 : (z == 2) ? W2 : W3;
    const size_t off = (size_t)z * DIM * DIM;
    int x = blockIdx.x * 32 + threadIdx.x;
    int y = blockIdx.y * 32 + threadIdx.y;
#pragma unroll
    for (int j = 0; j < 32; j += 8)
        tile[threadIdx.y + j][threadIdx.x] = S[(size_t)(y + j) * DIM + x];
    __syncthreads();
    x = blockIdx.y * 32 + threadIdx.x;
    y = blockIdx.x * 32 + threadIdx.y;
#pragma unroll
    for (int j = 0; j < 32; j += 8) {
        float v = tile[threadIdx.x][threadIdx.y + j];
        __nv_bfloat16 h, l;
        bsplit(v, h, l);
        Dh[off + (size_t)(y + j) * DIM + x] = h;
        Dl[off + (size_t)(y + j) * DIM + x] = l;
    }
}

// ============================================================
// elementwise fp32 -> bf16 hi/lo split (x only)
// ============================================================
__global__ __launch_bounds__(256) void split_convert(
    const float* __restrict__ S,
    __nv_bfloat16* __restrict__ Dh, __nv_bfloat16* __restrict__ Dl, int n4)
{
    int i = blockIdx.x * 256 + threadIdx.x;
    if (i >= n4) return;
    float4 v = *(const float4*)&S[i * 4];
    __nv_bfloat16 h0,h1,h2,h3,l0,l1,l2,l3;
    bsplit(v.x, h0, l0); bsplit(v.y, h1, l1);
    bsplit(v.z, h2, l2); bsplit(v.w, h3, l3);
    __nv_bfloat162* ph = (__nv_bfloat162*)&Dh[i * 4];
    __nv_bfloat162* pl = (__nv_bfloat162*)&Dl[i * 4];
    ph[0] = __nv_bfloat162(h0, h1); ph[1] = __nv_bfloat162(h2, h3);
    pl[0] = __nv_bfloat162(l0, l1); pl[1] = __nv_bfloat162(l2, l3);
}

// ============================================================
// bf16x3 GEMM core. Tile M128 x N128, BK=32, 8 warps of 64x32,
// ldmatrix fragments, cp.async double-buffered, 80KB smem ->
// 2 CTAs/SM.
// mode: 0 = fp32 C[row*ldc+col]; 1 = fp32 remap [h][row][t];
//       2 = bf16 split remap to Ch/Cl;
//       3 = per-tile exact top-16 candidates -> cand (scores).
// ============================================================
#define BK        32
#define SWW       20                 // words per smem row (16 data + 4 pad)
#define PLANE_B   10240              // 128 rows * 80 B
#define B_SECT    20480              // 2 A planes
#define BUF_B     40960              // 4 planes per buffer
#define GSMEM_BYTES 81920
#define SROW      132                // fp32 tile row stride (mode 3)

__device__ __forceinline__ void stage_tile(
    unsigned sbase, int buf, int k0, int tid,
    const __nv_bfloat16* gAh, const __nv_bfloat16* gAl,
    const __nv_bfloat16* gBh, const __nv_bfloat16* gBl,
    int lda, int ldb)
{
    const unsigned base = sbase + buf * BUF_B;
#pragma unroll
    for (int i = 0; i < 8; i++) {
        const int idx = tid + i * 256;         // 0..2047
        const int plane = idx >> 9;            // 0..3
        const int rem = idx & 511;
        const int row = rem >> 2, c4 = rem & 3;
        const __nv_bfloat16* pp =
            (plane == 0) ? gAh : (plane == 1) ? gAl : (plane == 2) ? gBh : gBl;
        const int ld = (plane < 2) ? lda : ldb;
        const __nv_bfloat16* src = pp + (size_t)row * ld + k0 + c4 * 8;
        const unsigned dst = base + plane * PLANE_B + row * 80 + c4 * 16;
        asm volatile("cp.async.cg.shared.global [%0], [%1], 16;"
                     :: "r"(dst), "l"(src));
    }
    asm volatile("cp.async.commit_group;");
}

__device__ __forceinline__ void gemm_core(
    unsigned sbase,
    const __nv_bfloat16* __restrict__ Ah, const __nv_bfloat16* __restrict__ Al,
    const __nv_bfloat16* __restrict__ Bh, const __nv_bfloat16* __restrict__ Bl,
    const float* __restrict__ bias, float* __restrict__ C,
    __nv_bfloat16* __restrict__ Ch, __nv_bfloat16* __restrict__ Cl,
    float2* __restrict__ cand, float* __restrict__ sf,
    int K, int lda, int ldb, int ldc, float alpha, int mode,
    int m0, int n0)
{
    const int tid  = threadIdx.x;
    const int lane = tid & 31;
    const int wid  = tid >> 5;
    const int wm   = (wid >> 2) * 64;     // 0,64
    const int wn   = (wid & 3) * 32;      // 0,32,64,96
    const int g    = lane >> 2;
    const int t    = lane & 3;
    const int sub    = lane >> 3;
    const int subrow = lane & 7;
    const int a_off = ((sub & 1) * 8 + subrow) * SWW + (sub >> 1) * 4;
    const int b_off = ((sub >> 1) * 8 + subrow) * SWW + (sub & 1) * 4;
    const unsigned FULL = 0xffffffffu;

    const __nv_bfloat16* gAh = Ah + (size_t)m0 * lda;
    const __nv_bfloat16* gAl = Al + (size_t)m0 * lda;
    const __nv_bfloat16* gBh = Bh + (size_t)n0 * ldb;
    const __nv_bfloat16* gBl = Bl + (size_t)n0 * ldb;

    float acc[4][4][4];
#pragma unroll
    for (int mt = 0; mt < 4; mt++)
#pragma unroll
        for (int nt = 0; nt < 4; nt++)
#pragma unroll
            for (int e = 0; e < 4; e++) acc[mt][nt][e] = 0.0f;

    const int T = K / BK;
    stage_tile(sbase, 0, 0, tid, gAh, gAl, gBh, gBl, lda, ldb);

    for (int tt = 0; tt < T; tt++) {
        if (tt + 1 < T) {
            stage_tile(sbase, (tt + 1) & 1, (tt + 1) * BK, tid,
                       gAh, gAl, gBh, gBl, lda, ldb);
            asm volatile("cp.async.wait_group 1;");
        } else {
            asm volatile("cp.async.wait_group 0;");
        }
        __syncthreads();

        const unsigned base = sbase + (tt & 1) * BUF_B;
#pragma unroll
        for (int ks = 0; ks < 2; ks++) {
            unsigned ah[4][4], al[4][4], bh[4][2], bl[4][2];
#pragma unroll
            for (int mt = 0; mt < 4; mt++) {
                const unsigned ad = base + ((wm + mt * 16) * SWW + ks * 8 + a_off) * 4;
                LDSM4(ah[mt][0], ah[mt][1], ah[mt][2], ah[mt][3], ad);
                LDSM4(al[mt][0], al[mt][1], al[mt][2], al[mt][3], ad + PLANE_B);
            }
#pragma unroll
            for (int np = 0; np < 2; np++) {
                const unsigned bd = base + B_SECT +
                                    ((wn + np * 16) * SWW + ks * 8 + b_off) * 4;
                unsigned r0, r1, r2, r3;
                LDSM4(r0, r1, r2, r3, bd);
                bh[2*np][0] = r0; bh[2*np][1] = r1;
                bh[2*np+1][0] = r2; bh[2*np+1][1] = r3;
                LDSM4(r0, r1, r2, r3, bd + PLANE_B);
                bl[2*np][0] = r0; bl[2*np][1] = r1;
                bl[2*np+1][0] = r2; bl[2*np+1][1] = r3;
            }
#pragma unroll
            for (int mt = 0; mt < 4; mt++)
#pragma unroll
                for (int nt = 0; nt < 4; nt++) {
                    mma_bf16(acc[mt][nt], al[mt], bh[nt]);
                    mma_bf16(acc[mt][nt], ah[mt], bl[nt]);
                    mma_bf16(acc[mt][nt], ah[mt], bh[nt]);
                }
        }
        __syncthreads();
    }

    if (mode == 3) {
        // ---- scores epilogue: stage fp32 tile, exact per-row top-16 ----
        int* sfi = (int*)sf;
#pragma unroll
        for (int mt = 0; mt < 4; mt++) {
            const int rowA = wm + mt * 16 + g;
            const int rowB = rowA + 8;
#pragma unroll
            for (int nt = 0; nt < 4; nt++) {
                const int col = wn + nt * 8 + 2 * t;
                sf[rowA * SROW + col]     = acc[mt][nt][0] * alpha;
                sf[rowA * SROW + col + 1] = acc[mt][nt][1] * alpha;
                sf[rowB * SROW + col]     = acc[mt][nt][2] * alpha;
                sf[rowB * SROW + col + 1] = acc[mt][nt][3] * alpha;
            }
        }
        __syncthreads();

        const int ktile = n0 >> 7;
        for (int rr = 0; rr < 16; rr++) {
            const int row = wid * 16 + rr;
            float4 v4 = *(const float4*)&sf[row * SROW + lane * 4];
            float vals[4] = {v4.x, v4.y, v4.z, v4.w};
            int   idxb[4];
#pragma unroll
            for (int j = 0; j < 4; j++) idxb[j] = n0 + lane * 4 + j;

            // tau = 16th largest of 32 lane maxima (exact bound)
            float mx = fmaxf(fmaxf(vals[0], vals[1]), fmaxf(vals[2], vals[3]));
            float sv = mx;
#pragma unroll
            for (int k = 2; k <= 32; k <<= 1) {
#pragma unroll
                for (int j = k >> 1; j > 0; j >>= 1) {
                    float o = __shfl_xor_sync(FULL, sv, j);
                    bool keepMin = (((lane & k) == 0) == ((lane & j) == 0));
                    sv = keepMin ? fminf(sv, o) : fmaxf(sv, o);
                }
            }
            const float tau = __shfl_sync(FULL, sv, 16);

            // ballot-compact survivors into this row's smem (cap 32)
            int cnt = 0;
#pragma unroll
            for (int j = 0; j < 4; j++) {
                bool p = (vals[j] >= tau);
                unsigned mk = __ballot_sync(FULL, p);
                if (p) {
                    int pos = cnt + __popc(mk & ((1u << lane) - 1u));
                    if (pos < 32) {
                        sf[row * SROW + pos]       = vals[j];
                        sfi[row * SROW + 32 + pos] = idxb[j];
                    }
                }
                cnt += __popc(mk);
            }
            __syncwarp();

            float cv; int ci;
            if (cnt <= 32) {
                cv = (lane < cnt) ? sf[row * SROW + lane] : -1e30f;
                ci = (lane < cnt) ? sfi[row * SROW + 32 + lane] : 0x7fffffff;
                // 32-lane bitonic DESC sort by (val desc, idx asc)
#pragma unroll
                for (int k = 2; k <= 32; k <<= 1) {
#pragma unroll
                    for (int j = k >> 1; j > 0; j >>= 1) {
                        float ov = __shfl_xor_sync(FULL, cv, j);
                        int   oi = __shfl_xor_sync(FULL, ci, j);
                        bool up = ((lane & k) == 0);
                        bool iLower = ((lane & j) == 0);
                        bool mineLarger = (cv > ov) || (cv == ov && ci < oi);
                        bool keepMine = (up == iLower) ? mineLarger : !mineLarger;
                        if (!keepMine) { cv = ov; ci = oi; }
                    }
                }
            } else {
                // rare fallback: exact 16-round argmax over 4 regs
                cv = -1e30f; ci = 0x7fffffff;
                for (int r = 0; r < 16; r++) {
                    float bv = -1e30f; int bi = 0x7fffffff;
#pragma unroll
                    for (int j = 0; j < 4; j++)
                        if (vals[j] > bv || (vals[j] == bv && idxb[j] < bi)) {
                            bv = vals[j]; bi = idxb[j];
                        }
#pragma unroll
                    for (int off = 16; off > 0; off >>= 1) {
                        float ov = __shfl_xor_sync(FULL, bv, off);
                        int   oi = __shfl_xor_sync(FULL, bi, off);
                        if (ov > bv || (ov == bv && oi < bi)) { bv = ov; bi = oi; }
                    }
#pragma unroll
                    for (int j = 0; j < 4; j++)
                        if (idxb[j] == bi) vals[j] = -1e30f;
                    if (lane == r) { cv = bv; ci = bi; }
                }
            }
            if (lane < 16)
                cand[((size_t)(m0 + row) * 16 + ktile) * 16 + lane] =
                    make_float2(cv, __int_as_float(ci));
        }
        return;
    }

    // ---- dense epilogues ----
#pragma unroll
    for (int mt = 0; mt < 4; mt++) {
        const int rowA = m0 + wm + mt * 16 + g;
        const int rowB = rowA + 8;
#pragma unroll
        for (int nt = 0; nt < 4; nt++) {
            const int col = n0 + wn + nt * 8 + 2 * t;
            float bx = 0.0f, by = 0.0f;
            if (bias) { bx = bias[col]; by = bias[col + 1]; }
            float lox = acc[mt][nt][0] * alpha + bx;
            float loy = acc[mt][nt][1] * alpha + by;
            float hix = acc[mt][nt][2] * alpha + bx;
            float hiy = acc[mt][nt][3] * alpha + by;
            if (mode == 0) {
                *(float2*)&C[(size_t)rowA * ldc + col] = make_float2(lox, loy);
                *(float2*)&C[(size_t)rowB * ldc + col] = make_float2(hix, hiy);
            } else if (mode == 1) {
                const int h = col >> 6, tc = col & 63;
                *(float2*)&C[((size_t)h * SQ + rowA) * HD + tc] = make_float2(lox, loy);
                *(float2*)&C[((size_t)h * SQ + rowB) * HD + tc] = make_float2(hix, hiy);
            } else {
                const int h = col >> 6, tc = col & 63;
                __nv_bfloat16 h0,h1,h2,h3,l0,l1,l2,l3;
                bsplit(lox, h0, l0); bsplit(loy, h1, l1);
                bsplit(hix, h2, l2); bsplit(hiy, h3, l3);
                *(__nv_bfloat162*)&Ch[((size_t)h * SQ + rowA) * HD + tc] = __nv_bfloat162(h0, h1);
                *(__nv_bfloat162*)&Cl[((size_t)h * SQ + rowA) * HD + tc] = __nv_bfloat162(l0, l1);
                *(__nv_bfloat162*)&Ch[((size_t)h * SQ + rowB) * HD + tc] = __nv_bfloat162(h2, h3);
                *(__nv_bfloat162*)&Cl[((size_t)h * SQ + rowB) * HD + tc] = __nv_bfloat162(l2, l3);
            }
        }
    }
}

// ---- out-proj wrapper ----
__global__ __launch_bounds__(256, 2) void nt_bf16x3_gemm(
    const __nv_bfloat16* __restrict__ Ah, const __nv_bfloat16* __restrict__ Al,
    const __nv_bfloat16* __restrict__ Bh, const __nv_bfloat16* __restrict__ Bl,
    const float* __restrict__ bias, float* __restrict__ C,
    int K, int lda, int ldb, int ldc, float alpha)
{
    extern __shared__ unsigned sm[];
    unsigned sbase = (unsigned)__cvta_generic_to_shared(sm);
    gemm_core(sbase, Ah, Al, Bh, Bl, bias, C, nullptr, nullptr,
              nullptr, nullptr,
              K, lda, ldb, ldc, alpha, 0,
              blockIdx.y * 128, blockIdx.x * 128);
}

// ---- scores wrapper: per-head, mode 3 (candidates) ----
__global__ __launch_bounds__(256, 2) void scores_gemm()
{
    extern __shared__ unsigned sm[];
    unsigned sbase = (unsigned)__cvta_generic_to_shared(sm);
    const int h = blockIdx.z;
    const size_t hs = (size_t)h * SQ * HD;
    gemm_core(sbase, g_Qh + hs, g_Ql + hs, g_Kh + hs, g_Kl + hs,
              nullptr, nullptr, nullptr, nullptr,
              g_cand + (size_t)h * SQ * 256, (float*)sm,
              HD, HD, HD, 0, 0.125f, 3,
              blockIdx.y * 128, blockIdx.x * 128);
}

// ---- fused QKV projection: blockIdx.z selects Q/K/V ----
__global__ __launch_bounds__(256, 2) void qkv_gemm(
    const float* __restrict__ bq, const float* __restrict__ bk,
    const float* __restrict__ bv)
{
    extern __shared__ unsigned sm[];
    unsigned sbase = (unsigned)__cvta_generic_to_shared(sm);
    const int z = blockIdx.z;
    const size_t DD = (size_t)DIM * DIM;
    const float* bias = (z == 0) ? bq : (z == 1) ? bk : bv;
    float* C = (z == 2) ? g_V : nullptr;
    __nv_bfloat16* Ch = (z == 0) ? g_Qh : (z == 1) ? g_Kh : nullptr;
    __nv_bfloat16* Cl = (z == 0) ? g_Ql : (z == 1) ? g_Kl : nullptr;
    gemm_core(sbase, g_xh, g_xl, g_WTh + z * DD, g_WTl + z * DD,
              bias, C, Ch, Cl, nullptr, nullptr,
              DIM, DIM, DIM, DIM, 1.0f, (z == 2) ? 1 : 2,
              blockIdx.y * 128, blockIdx.x * 128);
}

// ============================================================
// V column sums: stage A (64 partial blocks) + stage B (reduce)
// ============================================================
__global__ __launch_bounds__(256) void vsum_part()
{
    const int h  = blockIdx.x >> 2;
    const int qd = blockIdx.x & 3;
    const int t = threadIdx.x & 63;
    const int g = threadIdx.x >> 6;
    const float* Vh = g_V + (size_t)h * SQ * HD + (size_t)(qd * 512 + g * 128) * HD;
    float s = 0.0f;
    for (int r = 0; r < 128; ++r)
        s += Vh[(size_t)r * HD + t];
    __shared__ float red[4][64];
    red[g][t] = s;
    __syncthreads();
    if (g == 0)
        g_vsum_part[blockIdx.x][t] = red[0][t] + red[1][t] + red[2][t] + red[3][t];
}

__global__ __launch_bounds__(256) void vsum_reduce()
{
    const int i = blockIdx.x * 256 + threadIdx.x;   // 0..1023
    const int h = i >> 6, t = i & 63;
    g_vsum[i] = g_vsum_part[h * 4 + 0][t] + g_vsum_part[h * 4 + 1][t]
              + g_vsum_part[h * 4 + 2][t] + g_vsum_part[h * 4 + 3][t];
}

// ============================================================
// Final top-16 from 256 per-tile candidates + sparse softmax +
// V gather. One warp per (h, q). Output -> bf16 hi/lo planes.
// ============================================================
__global__ __launch_bounds__(128) void topk_attend()
{
    const unsigned FULL = 0xffffffffu;
    const int wslot = threadIdx.x >> 5;
    const int gwarp = (blockIdx.x * 128 + threadIdx.x) >> 5;
    const int lane  = threadIdx.x & 31;
    const int h = gwarp >> 11;
    const int q = gwarp & 2047;

    __shared__ float sval[4][64];
    __shared__ int   sidx[4][64];

    const float2* crow = g_cand + ((size_t)h * SQ + q) * 256;

    // load 8 candidates per lane (coalesced)
    float vals[8];
    int   idxb[8];
#pragma unroll
    for (int i = 0; i < 8; i++) {
        float2 c = crow[lane + 32 * i];
        vals[i] = c.x;
        idxb[i] = __float_as_int(c.y);
    }

    // tau = 16th largest of 32 lane maxima
    float mx = vals[0];
#pragma unroll
    for (int i = 1; i < 8; i++) mx = fmaxf(mx, vals[i]);
    float sv = mx;
#pragma unroll
    for (int k = 2; k <= 32; k <<= 1) {
#pragma unroll
        for (int j = k >> 1; j > 0; j >>= 1) {
            float o = __shfl_xor_sync(FULL, sv, j);
            bool keepMin = (((lane & k) == 0) == ((lane & j) == 0));
            sv = keepMin ? fminf(sv, o) : fmaxf(sv, o);
        }
    }
    const float tau = __shfl_sync(FULL, sv, 16);

    // ballot-compact survivors (cap 64)
    int cnt = 0;
#pragma unroll
    for (int i = 0; i < 8; i++) {
        bool p = (vals[i] >= tau);
        unsigned mk = __ballot_sync(FULL, p);
        if (p) {
            int pos = cnt + __popc(mk & ((1u << lane) - 1u));
            if (pos < 64) { sval[wslot][pos] = vals[i]; sidx[wslot][pos] = idxb[i]; }
        }
        cnt += __popc(mk);
    }
    __syncwarp();

    float fv = -1e30f;
    int   fi = 0;

    if (cnt <= 64) {
        float c0 = -1e30f, c1 = -1e30f;
        int   i0 = 0x7fffffff, i1 = 0x7fffffff;
        if (lane < cnt)      { c0 = sval[wslot][lane];      i0 = sidx[wslot][lane]; }
        if (lane + 32 < cnt) { c1 = sval[wslot][lane + 32]; i1 = sidx[wslot][lane + 32]; }
        for (int r = 0; r < 16; r++) {
            bool first = (c0 > c1) || (c0 == c1 && i0 < i1);
            float bv = first ? c0 : c1;
            int   bi = first ? i0 : i1;
            int   bl = lane * 2 + (first ? 0 : 1);
#pragma unroll
            for (int off = 16; off > 0; off >>= 1) {
                float ov = __shfl_down_sync(FULL, bv, off);
                int   oi = __shfl_down_sync(FULL, bi, off);
                int   ol = __shfl_down_sync(FULL, bl, off);
                if (ov > bv || (ov == bv && oi < bi)) { bv = ov; bi = oi; bl = ol; }
            }
            bv = __shfl_sync(FULL, bv, 0);
            bi = __shfl_sync(FULL, bi, 0);
            bl = __shfl_sync(FULL, bl, 0);
            if (lane == (bl >> 1)) {
                if ((bl & 1) == 0) { c0 = -1e30f; i0 = 0x7fffffff; }
                else               { c1 = -1e30f; i1 = 0x7fffffff; }
            }
            if (lane == r) { fv = bv; fi = bi; }
        }
    } else {
        // rare fallback: exact 16-round argmax over the 8 regs
        for (int r = 0; r < 16; r++) {
            float bv = -1e30f; int bi = 0x7fffffff;
#pragma unroll
            for (int i = 0; i < 8; i++)
                if (vals[i] > bv || (vals[i] == bv && idxb[i] < bi)) {
                    bv = vals[i]; bi = idxb[i];
                }
#pragma unroll
            for (int off = 16; off > 0; off >>= 1) {
                float ov = __shfl_xor_sync(FULL, bv, off);
                int   oi = __shfl_xor_sync(FULL, bi, off);
                if (ov > bv || (ov == bv && oi < bi)) { bv = ov; bi = oi; }
            }
#pragma unroll
            for (int i = 0; i < 8; i++)
                if (idxb[i] == bi) vals[i] = -1e30f;
            if (lane == r) { fv = bv; fi = bi; }
        }
    }

    // ---- sparse softmax (zeros participate) ----
    float m = __shfl_sync(FULL, fv, 0);
    m = fmaxf(m, 0.0f);
    float e = (lane < 16) ? expf(fv - m) : 0.0f;
    float z = e;
#pragma unroll
    for (int off = 16; off > 0; off >>= 1)
        z += __shfl_xor_sync(FULL, z, off);
    const float e0 = expf(-m);
    const float Z  = z + (float)(SQ - FACT) * e0;
    const float p0 = e0 / Z;
    const float w  = e / Z - p0;

    // ---- gather 16 V rows + p0 * vsum ----
    const float* Vh = g_V + (size_t)h * SQ * HD;
    float acc0 = p0 * g_vsum[h * HD + lane];
    float acc1 = p0 * g_vsum[h * HD + lane + 32];
#pragma unroll
    for (int i = 0; i < 16; i++) {
        const float wi  = __shfl_sync(FULL, w,  i);
        const int   idx = __shfl_sync(FULL, fi, i);
        const float* vr = Vh + (size_t)idx * HD;
        acc0 = fmaf(wi, vr[lane],      acc0);
        acc1 = fmaf(wi, vr[lane + 32], acc1);
    }
    const size_t o = (size_t)q * DIM + h * HD;
    __nv_bfloat16 h0, l0, h1, l1;
    bsplit(acc0, h0, l0);
    bsplit(acc1, h1, l1);
    g_ath[o + lane]      = h0;
    g_atl[o + lane]      = l0;
    g_ath[o + lane + 32] = h1;
    g_atl[o + lane + 32] = l1;
}

// ============================================================
extern "C" void kernel_launch(void* const* d_in, const int* in_sizes, int n_in,
                              void* d_out, int out_size)
{
    const float* x  = (const float*)d_in[0];
    const float* Wq = (const float*)d_in[1];
    const float* bq = (const float*)d_in[2];
    const float* Wk = (const float*)d_in[3];
    const float* bk = (const float*)d_in[4];
    const float* Wv = (const float*)d_in[5];
    const float* bv = (const float*)d_in[6];
    const float* Wo = (const float*)d_in[7];
    const float* bo = (const float*)d_in[8];
    float* out = (float*)d_out;

    __nv_bfloat16 *xh, *xl, *ath, *atl, *WTh, *WTl;
    cudaGetSymbolAddress((void**)&xh,  g_xh);  cudaGetSymbolAddress((void**)&xl,  g_xl);
    cudaGetSymbolAddress((void**)&ath, g_ath); cudaGetSymbolAddress((void**)&atl, g_atl);
    cudaGetSymbolAddress((void**)&WTh, g_WTh); cudaGetSymbolAddress((void**)&WTl, g_WTl);

    static int smem_set = 0;
    if (!smem_set) {
        cudaFuncSetAttribute(nt_bf16x3_gemm,
                             cudaFuncAttributeMaxDynamicSharedMemorySize, GSMEM_BYTES);
        cudaFuncSetAttribute(qkv_gemm,
                             cudaFuncAttributeMaxDynamicSharedMemorySize, GSMEM_BYTES);
        cudaFuncSetAttribute(scores_gemm,
                             cudaFuncAttributeMaxDynamicSharedMemorySize, GSMEM_BYTES);
        smem_set = 1;
    }

    const size_t DD = (size_t)DIM * DIM;

    // fused weight transposes + splits
    dim3 gT(DIM / 32, DIM / 32, 4);
    dim3 bT(32, 8);
    transpose_split4<<<gT, bT>>>(Wq, Wk, Wv, Wo, WTh, WTl);

    split_convert<<<(SQ * DIM / 4 + 255) / 256, 256>>>(x, xh, xl, SQ * DIM / 4);

    // fused Q/K/V projections (128x128 tiles)
    dim3 gQKV(DIM / 128, SQ / 128, 3);   // (8, 16, 3)
    qkv_gemm<<<gQKV, 256, GSMEM_BYTES>>>(bq, bk, bv);

    vsum_part<<<64, 256>>>();
    vsum_reduce<<<4, 256>>>();

    // scores GEMM + per-tile exact top-16 candidates (mode 3)
    dim3 gSc(SQ / 128, SQ / 128, NH);    // (16, 16, 16)
    scores_gemm<<<gSc, 256, GSMEM_BYTES>>>();

    topk_attend<<<(NH * SQ) / 4, 128>>>();

    // output projection (reads bf16 planes written by topk)
    dim3 gO(DIM / 128, SQ / 128, 1);     // (8, 16, 1)
    nt_bf16x3_gemm<<<gO, 256, GSMEM_BYTES>>>(
        ath, atl, WTh + 3 * DD, WTl + 3 * DD, bo, out,
        DIM, DIM, DIM, DIM, 1.0f);
}

// round 17
// speedup vs baseline: 1.2052x; 1.2052x over previous
#include <cuda_runtime.h>
#include <cuda_bf16.h>
#include <math.h>

#define SQ   2048
#define DIM  1024
#define NH   16
#define HD   64
#define FACT 16

// ---- scratch (device globals: the sanctioned no-alloc scratch path) ----
__device__ float g_V[NH * SQ * HD];              // 8 MB fp32 [h][s][hd]
__device__ float g_scoresH[(size_t)SQ * SQ];     // 16 MB fp32, ONE head (L2-resident)
__device__ float g_vsum[NH * HD];
__device__ float g_vsum_part[64][HD];

// bf16 split planes
__device__ __nv_bfloat16 g_xh[SQ * DIM],  g_xl[SQ * DIM];
__device__ __nv_bfloat16 g_ath[SQ * DIM], g_atl[SQ * DIM];   // attn out planes
__device__ __nv_bfloat16 g_WTh[4 * DIM * DIM], g_WTl[4 * DIM * DIM];
__device__ __nv_bfloat16 g_Qh[NH * SQ * HD], g_Ql[NH * SQ * HD];
__device__ __nv_bfloat16 g_Kh[NH * SQ * HD], g_Kl[NH * SQ * HD];

// ============================================================
// helpers
// ============================================================
__device__ __forceinline__ void bsplit(float v, __nv_bfloat16& h, __nv_bfloat16& l) {
    h = __float2bfloat16(v);
    l = __float2bfloat16(v - __bfloat162float(h));
}

__device__ __forceinline__ void mma_bf16(float* c, const unsigned* a, const unsigned* b) {
    asm volatile(
        "mma.sync.aligned.m16n8k16.row.col.f32.bf16.bf16.f32 "
        "{%0,%1,%2,%3}, {%4,%5,%6,%7}, {%8,%9}, {%0,%1,%2,%3};"
        : "+f"(c[0]), "+f"(c[1]), "+f"(c[2]), "+f"(c[3])
        : "r"(a[0]), "r"(a[1]), "r"(a[2]), "r"(a[3]),
          "r"(b[0]), "r"(b[1]));
}

#define LDSM4(R0, R1, R2, R3, A)                                          \
    asm volatile("ldmatrix.sync.aligned.m8n8.x4.shared.b16 "              \
                 "{%0,%1,%2,%3}, [%4];"                                   \
                 : "=r"(R0), "=r"(R1), "=r"(R2), "=r"(R3) : "r"(A))

// ============================================================
// fused 4x 1024x1024 transpose + bf16 hi/lo split (z = which W)
// ============================================================
__global__ __launch_bounds__(256) void transpose_split4(
    const float* __restrict__ W0, const float* __restrict__ W1,
    const float* __restrict__ W2, const float* __restrict__ W3,
    __nv_bfloat16* __restrict__ Dh, __nv_bfloat16* __restrict__ Dl)
{
    __shared__ float tile[32][33];
    const int z = blockIdx.z;
    const float* S = (z == 0) ? W0 : (z == 1) ? W1 : (z == 2) ? W2 : W3;
    const size_t off = (size_t)z * DIM * DIM;
    int x = blockIdx.x * 32 + threadIdx.x;
    int y = blockIdx.y * 32 + threadIdx.y;
#pragma unroll
    for (int j = 0; j < 32; j += 8)
        tile[threadIdx.y + j][threadIdx.x] = S[(size_t)(y + j) * DIM + x];
    __syncthreads();
    x = blockIdx.y * 32 + threadIdx.x;
    y = blockIdx.x * 32 + threadIdx.y;
#pragma unroll
    for (int j = 0; j < 32; j += 8) {
        float v = tile[threadIdx.x][threadIdx.y + j];
        __nv_bfloat16 h, l;
        bsplit(v, h, l);
        Dh[off + (size_t)(y + j) * DIM + x] = h;
        Dl[off + (size_t)(y + j) * DIM + x] = l;
    }
}

// ============================================================
// elementwise fp32 -> bf16 hi/lo split (x only)
// ============================================================
__global__ __launch_bounds__(256) void split_convert(
    const float* __restrict__ S,
    __nv_bfloat16* __restrict__ Dh, __nv_bfloat16* __restrict__ Dl, int n4)
{
    int i = blockIdx.x * 256 + threadIdx.x;
    if (i >= n4) return;
    float4 v = *(const float4*)&S[i * 4];
    __nv_bfloat16 h0,h1,h2,h3,l0,l1,l2,l3;
    bsplit(v.x, h0, l0); bsplit(v.y, h1, l1);
    bsplit(v.z, h2, l2); bsplit(v.w, h3, l3);
    __nv_bfloat162* ph = (__nv_bfloat162*)&Dh[i * 4];
    __nv_bfloat162* pl = (__nv_bfloat162*)&Dl[i * 4];
    ph[0] = __nv_bfloat162(h0, h1); ph[1] = __nv_bfloat162(h2, h3);
    pl[0] = __nv_bfloat162(l0, l1); pl[1] = __nv_bfloat162(l2, l3);
}

// ============================================================
// bf16x3 GEMM core. Tile M128 x N128, BK=32, 8 warps of 64x32,
// ldmatrix fragments, cp.async double-buffered, 80KB smem ->
// 2 CTAs/SM.
// mode: 0 = fp32 C[row*ldc+col]; 1 = fp32 remap [h][row][t];
//       2 = bf16 split remap to Ch/Cl.
// ============================================================
#define BK        32
#define SWW       20                 // words per smem row (16 data + 4 pad)
#define PLANE_B   10240              // 128 rows * 80 B
#define B_SECT    20480              // 2 A planes
#define BUF_B     40960              // 4 planes per buffer
#define GSMEM_BYTES 81920

__device__ __forceinline__ void stage_tile(
    unsigned sbase, int buf, int k0, int tid,
    const __nv_bfloat16* gAh, const __nv_bfloat16* gAl,
    const __nv_bfloat16* gBh, const __nv_bfloat16* gBl,
    int lda, int ldb)
{
    const unsigned base = sbase + buf * BUF_B;
#pragma unroll
    for (int i = 0; i < 8; i++) {
        const int idx = tid + i * 256;         // 0..2047
        const int plane = idx >> 9;            // 0..3
        const int rem = idx & 511;
        const int row = rem >> 2, c4 = rem & 3;
        const __nv_bfloat16* pp =
            (plane == 0) ? gAh : (plane == 1) ? gAl : (plane == 2) ? gBh : gBl;
        const int ld = (plane < 2) ? lda : ldb;
        const __nv_bfloat16* src = pp + (size_t)row * ld + k0 + c4 * 8;
        const unsigned dst = base + plane * PLANE_B + row * 80 + c4 * 16;
        asm volatile("cp.async.cg.shared.global [%0], [%1], 16;"
                     :: "r"(dst), "l"(src));
    }
    asm volatile("cp.async.commit_group;");
}

__device__ __forceinline__ void gemm_core(
    unsigned sbase,
    const __nv_bfloat16* __restrict__ Ah, const __nv_bfloat16* __restrict__ Al,
    const __nv_bfloat16* __restrict__ Bh, const __nv_bfloat16* __restrict__ Bl,
    const float* __restrict__ bias, float* __restrict__ C,
    __nv_bfloat16* __restrict__ Ch, __nv_bfloat16* __restrict__ Cl,
    int K, int lda, int ldb, int ldc, float alpha, int mode,
    int m0, int n0)
{
    const int tid  = threadIdx.x;
    const int lane = tid & 31;
    const int wid  = tid >> 5;
    const int wm   = (wid >> 2) * 64;     // 0,64
    const int wn   = (wid & 3) * 32;      // 0,32,64,96
    const int g    = lane >> 2;
    const int t    = lane & 3;
    const int sub    = lane >> 3;
    const int subrow = lane & 7;
    const int a_off = ((sub & 1) * 8 + subrow) * SWW + (sub >> 1) * 4;
    const int b_off = ((sub >> 1) * 8 + subrow) * SWW + (sub & 1) * 4;

    const __nv_bfloat16* gAh = Ah + (size_t)m0 * lda;
    const __nv_bfloat16* gAl = Al + (size_t)m0 * lda;
    const __nv_bfloat16* gBh = Bh + (size_t)n0 * ldb;
    const __nv_bfloat16* gBl = Bl + (size_t)n0 * ldb;

    float acc[4][4][4];
#pragma unroll
    for (int mt = 0; mt < 4; mt++)
#pragma unroll
        for (int nt = 0; nt < 4; nt++)
#pragma unroll
            for (int e = 0; e < 4; e++) acc[mt][nt][e] = 0.0f;

    const int T = K / BK;
    stage_tile(sbase, 0, 0, tid, gAh, gAl, gBh, gBl, lda, ldb);

    for (int tt = 0; tt < T; tt++) {
        if (tt + 1 < T) {
            stage_tile(sbase, (tt + 1) & 1, (tt + 1) * BK, tid,
                       gAh, gAl, gBh, gBl, lda, ldb);
            asm volatile("cp.async.wait_group 1;");
        } else {
            asm volatile("cp.async.wait_group 0;");
        }
        __syncthreads();

        const unsigned base = sbase + (tt & 1) * BUF_B;
#pragma unroll
        for (int ks = 0; ks < 2; ks++) {
            unsigned ah[4][4], al[4][4], bh[4][2], bl[4][2];
#pragma unroll
            for (int mt = 0; mt < 4; mt++) {
                const unsigned ad = base + ((wm + mt * 16) * SWW + ks * 8 + a_off) * 4;
                LDSM4(ah[mt][0], ah[mt][1], ah[mt][2], ah[mt][3], ad);
                LDSM4(al[mt][0], al[mt][1], al[mt][2], al[mt][3], ad + PLANE_B);
            }
#pragma unroll
            for (int np = 0; np < 2; np++) {
                const unsigned bd = base + B_SECT +
                                    ((wn + np * 16) * SWW + ks * 8 + b_off) * 4;
                unsigned r0, r1, r2, r3;
                LDSM4(r0, r1, r2, r3, bd);
                bh[2*np][0] = r0; bh[2*np][1] = r1;
                bh[2*np+1][0] = r2; bh[2*np+1][1] = r3;
                LDSM4(r0, r1, r2, r3, bd + PLANE_B);
                bl[2*np][0] = r0; bl[2*np][1] = r1;
                bl[2*np+1][0] = r2; bl[2*np+1][1] = r3;
            }
#pragma unroll
            for (int mt = 0; mt < 4; mt++)
#pragma unroll
                for (int nt = 0; nt < 4; nt++) {
                    mma_bf16(acc[mt][nt], al[mt], bh[nt]);
                    mma_bf16(acc[mt][nt], ah[mt], bl[nt]);
                    mma_bf16(acc[mt][nt], ah[mt], bh[nt]);
                }
        }
        __syncthreads();
    }

    // ---- epilogue ----
#pragma unroll
    for (int mt = 0; mt < 4; mt++) {
        const int rowA = m0 + wm + mt * 16 + g;
        const int rowB = rowA + 8;
#pragma unroll
        for (int nt = 0; nt < 4; nt++) {
            const int col = n0 + wn + nt * 8 + 2 * t;
            float bx = 0.0f, by = 0.0f;
            if (bias) { bx = bias[col]; by = bias[col + 1]; }
            float lox = acc[mt][nt][0] * alpha + bx;
            float loy = acc[mt][nt][1] * alpha + by;
            float hix = acc[mt][nt][2] * alpha + bx;
            float hiy = acc[mt][nt][3] * alpha + by;
            if (mode == 0) {
                *(float2*)&C[(size_t)rowA * ldc + col] = make_float2(lox, loy);
                *(float2*)&C[(size_t)rowB * ldc + col] = make_float2(hix, hiy);
            } else if (mode == 1) {
                const int h = col >> 6, tc = col & 63;
                *(float2*)&C[((size_t)h * SQ + rowA) * HD + tc] = make_float2(lox, loy);
                *(float2*)&C[((size_t)h * SQ + rowB) * HD + tc] = make_float2(hix, hiy);
            } else {
                const int h = col >> 6, tc = col & 63;
                __nv_bfloat16 h0,h1,h2,h3,l0,l1,l2,l3;
                bsplit(lox, h0, l0); bsplit(loy, h1, l1);
                bsplit(hix, h2, l2); bsplit(hiy, h3, l3);
                *(__nv_bfloat162*)&Ch[((size_t)h * SQ + rowA) * HD + tc] = __nv_bfloat162(h0, h1);
                *(__nv_bfloat162*)&Cl[((size_t)h * SQ + rowA) * HD + tc] = __nv_bfloat162(l0, l1);
                *(__nv_bfloat162*)&Ch[((size_t)h * SQ + rowB) * HD + tc] = __nv_bfloat162(h2, h3);
                *(__nv_bfloat162*)&Cl[((size_t)h * SQ + rowB) * HD + tc] = __nv_bfloat162(l2, l3);
            }
        }
    }
}

// ---- generic wrapper (out-proj) ----
__global__ __launch_bounds__(256, 2) void nt_bf16x3_gemm(
    const __nv_bfloat16* __restrict__ Ah, const __nv_bfloat16* __restrict__ Al,
    const __nv_bfloat16* __restrict__ Bh, const __nv_bfloat16* __restrict__ Bl,
    const float* __restrict__ bias, float* __restrict__ C,
    int K, int lda, int ldb, int ldc, float alpha)
{
    extern __shared__ unsigned sm[];
    unsigned sbase = (unsigned)__cvta_generic_to_shared(sm);
    gemm_core(sbase, Ah, Al, Bh, Bl, bias, C, nullptr, nullptr,
              K, lda, ldb, ldc, alpha, 0,
              blockIdx.y * 128, blockIdx.x * 128);
}

// ---- per-head scores GEMM -> L2-resident single-head buffer ----
__global__ __launch_bounds__(256, 2) void scores_gemm(int h)
{
    extern __shared__ unsigned sm[];
    unsigned sbase = (unsigned)__cvta_generic_to_shared(sm);
    const size_t hs = (size_t)h * SQ * HD;
    gemm_core(sbase, g_Qh + hs, g_Ql + hs, g_Kh + hs, g_Kl + hs,
              nullptr, g_scoresH, nullptr, nullptr,
              HD, HD, HD, SQ, 0.125f, 0,
              blockIdx.y * 128, blockIdx.x * 128);
}

// ---- fused QKV projection: blockIdx.z selects Q/K/V ----
__global__ __launch_bounds__(256, 2) void qkv_gemm(
    const float* __restrict__ bq, const float* __restrict__ bk,
    const float* __restrict__ bv)
{
    extern __shared__ unsigned sm[];
    unsigned sbase = (unsigned)__cvta_generic_to_shared(sm);
    const int z = blockIdx.z;
    const size_t DD = (size_t)DIM * DIM;
    const float* bias = (z == 0) ? bq : (z == 1) ? bk : bv;
    float* C = (z == 2) ? g_V : nullptr;
    __nv_bfloat16* Ch = (z == 0) ? g_Qh : (z == 1) ? g_Kh : nullptr;
    __nv_bfloat16* Cl = (z == 0) ? g_Ql : (z == 1) ? g_Kl : nullptr;
    gemm_core(sbase, g_xh, g_xl, g_WTh + z * DD, g_WTl + z * DD,
              bias, C, Ch, Cl,
              DIM, DIM, DIM, DIM, 1.0f, (z == 2) ? 1 : 2,
              blockIdx.y * 128, blockIdx.x * 128);
}

// ============================================================
// V column sums: stage A (64 partial blocks) + stage B (reduce)
// ============================================================
__global__ __launch_bounds__(256) void vsum_part()
{
    const int h  = blockIdx.x >> 2;
    const int qd = blockIdx.x & 3;
    const int t = threadIdx.x & 63;
    const int g = threadIdx.x >> 6;
    const float* Vh = g_V + (size_t)h * SQ * HD + (size_t)(qd * 512 + g * 128) * HD;
    float s = 0.0f;
    for (int r = 0; r < 128; ++r)
        s += Vh[(size_t)r * HD + t];
    __shared__ float red[4][64];
    red[g][t] = s;
    __syncthreads();
    if (g == 0)
        g_vsum_part[blockIdx.x][t] = red[0][t] + red[1][t] + red[2][t] + red[3][t];
}

__global__ __launch_bounds__(256) void vsum_reduce()
{
    const int i = blockIdx.x * 256 + threadIdx.x;   // 0..1023
    const int h = i >> 6, t = i & 63;
    g_vsum[i] = g_vsum_part[h * 4 + 0][t] + g_vsum_part[h * 4 + 1][t]
              + g_vsum_part[h * 4 + 2][t] + g_vsum_part[h * 4 + 3][t];
}

// ============================================================
// Top-16 (exact fp32, threshold-pruned) + sparse softmax +
// V gather for ONE head. One warp per q. Output -> bf16 planes.
// ============================================================
__global__ __launch_bounds__(128) void topk_attend(int h)
{
    const unsigned FULL = 0xffffffffu;
    const int wslot = threadIdx.x >> 5;
    const int q     = blockIdx.x * 4 + wslot;
    const int lane  = threadIdx.x & 31;

    __shared__ float sval[4][64];
    __shared__ int   sidx[4][64];

    const float* row = g_scoresH + (size_t)q * SQ;

    // ---- pass 1: per-lane max over 64 strided elements ----
    float mx = -1e30f;
#pragma unroll
    for (int c = 0; c < 16; c++) {
        float4 v = *(const float4*)&row[c * 128 + lane * 4];
        mx = fmaxf(mx, fmaxf(fmaxf(v.x, v.y), fmaxf(v.z, v.w)));
    }
    float sv = mx;
#pragma unroll
    for (int k = 2; k <= 32; k <<= 1) {
#pragma unroll
        for (int j = k >> 1; j > 0; j >>= 1) {
            float o = __shfl_xor_sync(FULL, sv, j);
            bool keepMin = (((lane & k) == 0) == ((lane & j) == 0));
            sv = keepMin ? fminf(sv, o) : fmaxf(sv, o);
        }
    }
    const float tau = __shfl_sync(FULL, sv, 16);

    // ---- pass 2: ballot-compact survivors (val >= tau) ----
    int cnt = 0;
#pragma unroll
    for (int c = 0; c < 16; c++) {
        const int base = c * 128 + lane * 4;
        float4 v = *(const float4*)&row[base];
        float vals[4] = {v.x, v.y, v.z, v.w};
#pragma unroll
        for (int j = 0; j < 4; j++) {
            bool p = (vals[j] >= tau);
            unsigned mk = __ballot_sync(FULL, p);
            if (p) {
                int pos = cnt + __popc(mk & ((1u << lane) - 1u));
                if (pos < 64) { sval[wslot][pos] = vals[j]; sidx[wslot][pos] = base + j; }
            }
            cnt += __popc(mk);
        }
    }
    __syncwarp();

    float fv = -1e30f;
    int   fi = 0;

    if (cnt <= 64) {
        float c0 = -1e30f, c1 = -1e30f;
        int   i0 = 0x7fffffff, i1 = 0x7fffffff;
        if (lane < cnt)      { c0 = sval[wslot][lane];      i0 = sidx[wslot][lane]; }
        if (lane + 32 < cnt) { c1 = sval[wslot][lane + 32]; i1 = sidx[wslot][lane + 32]; }
        for (int r = 0; r < 16; r++) {
            bool first = (c0 > c1) || (c0 == c1 && i0 < i1);
            float bv = first ? c0 : c1;
            int   bi = first ? i0 : i1;
            int   bl = lane * 2 + (first ? 0 : 1);
#pragma unroll
            for (int off = 16; off > 0; off >>= 1) {
                float ov = __shfl_down_sync(FULL, bv, off);
                int   oi = __shfl_down_sync(FULL, bi, off);
                int   ol = __shfl_down_sync(FULL, bl, off);
                if (ov > bv || (ov == bv && oi < bi)) { bv = ov; bi = oi; bl = ol; }
            }
            bv = __shfl_sync(FULL, bv, 0);
            bi = __shfl_sync(FULL, bi, 0);
            bl = __shfl_sync(FULL, bl, 0);
            if (lane == (bl >> 1)) {
                if ((bl & 1) == 0) { c0 = -1e30f; i0 = 0x7fffffff; }
                else               { c1 = -1e30f; i1 = 0x7fffffff; }
            }
            if (lane == r) { fv = bv; fi = bi; }
        }
    } else {
        float lv[16];
        int   li[16];
#pragma unroll
        for (int i = 0; i < 16; i++) { lv[i] = -1e30f; li[i] = 0; }
#pragma unroll 4
        for (int c = 0; c < 16; c++) {
            const int base = c * 128 + lane * 4;
            float4 v4 = *(const float4*)&row[base];
            float vals[4] = {v4.x, v4.y, v4.z, v4.w};
#pragma unroll
            for (int j = 0; j < 4; j++) {
                const float val = vals[j];
                if (val > lv[15]) {
                    lv[15] = val; li[15] = base + j;
#pragma unroll
                    for (int p = 15; p >= 1; --p) {
                        if (lv[p] > lv[p - 1]) {
                            float tv = lv[p]; lv[p] = lv[p - 1]; lv[p - 1] = tv;
                            int   ti = li[p]; li[p] = li[p - 1]; li[p - 1] = ti;
                        }
                    }
                }
            }
        }
        for (int r = 0; r < 16; r++) {
            float bv = lv[0]; int bi = li[0]; int bl = lane;
#pragma unroll
            for (int off = 16; off > 0; off >>= 1) {
                float ov = __shfl_down_sync(FULL, bv, off);
                int   oi = __shfl_down_sync(FULL, bi, off);
                int   ol = __shfl_down_sync(FULL, bl, off);
                if (ov > bv || (ov == bv && oi < bi)) { bv = ov; bi = oi; bl = ol; }
            }
            bv = __shfl_sync(FULL, bv, 0);
            bi = __shfl_sync(FULL, bi, 0);
            bl = __shfl_sync(FULL, bl, 0);
            if (lane == bl && li[0] == bi) {
#pragma unroll
                for (int p = 0; p < 15; p++) { lv[p] = lv[p + 1]; li[p] = li[p + 1]; }
                lv[15] = -1e30f;
            }
            if (lane == r) { fv = bv; fi = bi; }
        }
    }

    // ---- sparse softmax (zeros participate) ----
    float m = __shfl_sync(FULL, fv, 0);
    m = fmaxf(m, 0.0f);
    float e = (lane < 16) ? expf(fv - m) : 0.0f;
    float z = e;
#pragma unroll
    for (int off = 16; off > 0; off >>= 1)
        z += __shfl_xor_sync(FULL, z, off);
    const float e0 = expf(-m);
    const float Z  = z + (float)(SQ - FACT) * e0;
    const float p0 = e0 / Z;
    const float w  = e / Z - p0;

    // ---- gather 16 V rows + p0 * vsum ----
    const float* Vh = g_V + (size_t)h * SQ * HD;
    float acc0 = p0 * g_vsum[h * HD + lane];
    float acc1 = p0 * g_vsum[h * HD + lane + 32];
#pragma unroll
    for (int i = 0; i < 16; i++) {
        const float wi  = __shfl_sync(FULL, w,  i);
        const int   idx = __shfl_sync(FULL, fi, i);
        const float* vr = Vh + (size_t)idx * HD;
        acc0 = fmaf(wi, vr[lane],      acc0);
        acc1 = fmaf(wi, vr[lane + 32], acc1);
    }
    const size_t o = (size_t)q * DIM + h * HD;
    __nv_bfloat16 h0, l0, h1, l1;
    bsplit(acc0, h0, l0);
    bsplit(acc1, h1, l1);
    g_ath[o + lane]      = h0;
    g_atl[o + lane]      = l0;
    g_ath[o + lane + 32] = h1;
    g_atl[o + lane + 32] = l1;
}

// ============================================================
extern "C" void kernel_launch(void* const* d_in, const int* in_sizes, int n_in,
                              void* d_out, int out_size)
{
    const float* x  = (const float*)d_in[0];
    const float* Wq = (const float*)d_in[1];
    const float* bq = (const float*)d_in[2];
    const float* Wk = (const float*)d_in[3];
    const float* bk = (const float*)d_in[4];
    const float* Wv = (const float*)d_in[5];
    const float* bv = (const float*)d_in[6];
    const float* Wo = (const float*)d_in[7];
    const float* bo = (const float*)d_in[8];
    float* out = (float*)d_out;

    __nv_bfloat16 *xh, *xl, *ath, *atl, *WTh, *WTl;
    cudaGetSymbolAddress((void**)&xh,  g_xh);  cudaGetSymbolAddress((void**)&xl,  g_xl);
    cudaGetSymbolAddress((void**)&ath, g_ath); cudaGetSymbolAddress((void**)&atl, g_atl);
    cudaGetSymbolAddress((void**)&WTh, g_WTh); cudaGetSymbolAddress((void**)&WTl, g_WTl);

    static int smem_set = 0;
    if (!smem_set) {
        cudaFuncSetAttribute(nt_bf16x3_gemm,
                             cudaFuncAttributeMaxDynamicSharedMemorySize, GSMEM_BYTES);
        cudaFuncSetAttribute(qkv_gemm,
                             cudaFuncAttributeMaxDynamicSharedMemorySize, GSMEM_BYTES);
        cudaFuncSetAttribute(scores_gemm,
                             cudaFuncAttributeMaxDynamicSharedMemorySize, GSMEM_BYTES);
        smem_set = 1;
    }

    const size_t DD = (size_t)DIM * DIM;

    // fused weight transposes + splits
    dim3 gT(DIM / 32, DIM / 32, 4);
    dim3 bT(32, 8);
    transpose_split4<<<gT, bT>>>(Wq, Wk, Wv, Wo, WTh, WTl);

    split_convert<<<(SQ * DIM / 4 + 255) / 256, 256>>>(x, xh, xl, SQ * DIM / 4);

    // fused Q/K/V projections (128x128 tiles)
    dim3 gQKV(DIM / 128, SQ / 128, 3);   // (8, 16, 3)
    qkv_gemm<<<gQKV, 256, GSMEM_BYTES>>>(bq, bk, bv);

    vsum_part<<<64, 256>>>();
    vsum_reduce<<<4, 256>>>();

    // per-head: scores into L2-resident 16MB buffer, then topk
    dim3 gSc(SQ / 128, SQ / 128);        // (16, 16)
    for (int h = 0; h < NH; h++) {
        scores_gemm<<<gSc, 256, GSMEM_BYTES>>>(h);
        topk_attend<<<SQ / 4, 128>>>(h);
    }

    // output projection (reads bf16 planes written by topk)
    dim3 gO(DIM / 128, SQ / 128, 1);     // (8, 16, 1)
    nt_bf16x3_gemm<<<gO, 256, GSMEM_BYTES>>>(
        ath, atl, WTh + 3 * DD, WTl + 3 * DD, bo, out,
        DIM, DIM, DIM, DIM, 1.0f);
}